// round 1
// baseline (speedup 1.0000x reference)
#include <cuda_runtime.h>
#include <cstdint>

// ---------------- constants ----------------
#define B_   8
#define CIN  64
#define COUT 64
#define H_   96
#define W_   96
#define HW   (H_*W_)          // 9216
#define KK   9                // 3x3 taps
#define OFFC 18               // 2*KK offset channels

// ---------------- scratch (__device__ globals; no allocation allowed) ----------------
__device__ float g_xT[B_ * HW * CIN];       // NHWC transposed x  (18.9 MB)
__device__ float g_off[B_ * OFFC * HW];     // offset field       (5.3 MB)
__device__ float g_wT[KK * CIN * COUT];     // weight as [kk][c][oc]

// ============================================================
// Kernel 1: NCHW -> NHWC transpose of x (tiled via smem)
// view per b: A[64][9216] -> out[9216][64]
// grid (HW/32, CIN/32, B), block (32,8)
// ============================================================
__global__ __launch_bounds__(256) void transpose_x_kernel(const float* __restrict__ x)
{
    __shared__ float tile[32][33];
    int b   = blockIdx.z;
    int hw0 = blockIdx.x * 32;
    int c0  = blockIdx.y * 32;
    int tx = threadIdx.x, ty = threadIdx.y;

    const float* src = x + (size_t)b * CIN * HW;
#pragma unroll
    for (int i = 0; i < 32; i += 8)
        tile[ty + i][tx] = src[(size_t)(c0 + ty + i) * HW + hw0 + tx];
    __syncthreads();
    float* dst = g_xT + (size_t)b * HW * CIN;
#pragma unroll
    for (int i = 0; i < 32; i += 8)
        dst[(size_t)(hw0 + ty + i) * CIN + c0 + tx] = tile[tx][ty + i];
}

// ============================================================
// Kernel 2: weight (oc, c, kk) -> wT[kk][c][oc]
// ============================================================
__global__ __launch_bounds__(256) void transpose_w_kernel(const float* __restrict__ w)
{
    int idx = blockIdx.x * 256 + threadIdx.x;
    if (idx < COUT * CIN * KK) {
        int kk = idx % KK;
        int c  = (idx / KK) % CIN;
        int oc = idx / (KK * CIN);
        g_wT[(kk * CIN + c) * COUT + oc] = w[idx];
    }
}

// ============================================================
// Kernel 3: offset conv  (x: NCHW read, coalesced along W)
// out: g_off[b][o][ho][wo],  o in [0,18)
// block: 256 threads = 32(wo) x 8(ho); grid (3, 12, 8)
// smem: off_w staged as wS[c*9+kh*3+kw][20] (18 oc + 2 pad), LDS.128-friendly
// ============================================================
__global__ __launch_bounds__(256) void offset_conv_kernel(
    const float* __restrict__ x,
    const float* __restrict__ off_w,
    const float* __restrict__ off_b)
{
    __shared__ float wS[576][20];   // 46080 B

    int tid = threadIdx.x;
    // stage weights: off_w linear i = o*576 + r, r = c*9 + kh*3 + kw
    for (int i = tid; i < OFFC * 576; i += 256) {
        int o = i / 576;
        int r = i % 576;
        wS[r][o] = off_w[i];
    }
    // zero the pad columns (read by the last float4 but never accumulated past 17;
    // we read oc 16..17 as scalars, so pads are actually unread, but keep them clean)
    for (int r = tid; r < 576; r += 256) { wS[r][18] = 0.f; wS[r][19] = 0.f; }
    __syncthreads();

    int b   = blockIdx.z;
    int wo  = blockIdx.x * 32 + (tid & 31);
    int ho  = blockIdx.y * 8  + (tid >> 5);

    float acc[18];
#pragma unroll
    for (int o = 0; o < 18; ++o) acc[o] = 0.f;

    const float* xb = x + (size_t)b * CIN * HW;

    for (int c = 0; c < CIN; ++c) {
        const float* xc = xb + (size_t)c * HW;
#pragma unroll
        for (int kh = 0; kh < 3; ++kh) {
            int y = ho + kh - 1;
            bool vy = ((unsigned)y < (unsigned)H_);
#pragma unroll
            for (int kw = 0; kw < 3; ++kw) {
                int xx = wo + kw - 1;
                float xv = 0.f;
                if (vy && (unsigned)xx < (unsigned)W_)
                    xv = __ldg(xc + y * W_ + xx);
                const float* wr = &wS[c * 9 + kh * 3 + kw][0];
                float4 w0 = *(const float4*)(wr + 0);
                float4 w1 = *(const float4*)(wr + 4);
                float4 w2 = *(const float4*)(wr + 8);
                float4 w3 = *(const float4*)(wr + 12);
                float  wa = wr[16], wb = wr[17];
                acc[0]  += xv * w0.x;  acc[1]  += xv * w0.y;
                acc[2]  += xv * w0.z;  acc[3]  += xv * w0.w;
                acc[4]  += xv * w1.x;  acc[5]  += xv * w1.y;
                acc[6]  += xv * w1.z;  acc[7]  += xv * w1.w;
                acc[8]  += xv * w2.x;  acc[9]  += xv * w2.y;
                acc[10] += xv * w2.z;  acc[11] += xv * w2.w;
                acc[12] += xv * w3.x;  acc[13] += xv * w3.y;
                acc[14] += xv * w3.z;  acc[15] += xv * w3.w;
                acc[16] += xv * wa;    acc[17] += xv * wb;
            }
        }
    }

#pragma unroll
    for (int o = 0; o < 18; ++o) {
        g_off[((size_t)(b * OFFC + o) * H_ + ho) * W_ + wo] = acc[o] + __ldg(&off_b[o]);
    }
}

// ============================================================
// Kernel 4: deformable conv main
// block tile: 64 pixels (4 ho x 16 wo) x 64 oc, 256 threads
// grid (96/16=6, 96/4=24, 8)
// per tap kk: sample 64pix x 64ch into smem, stage wT chunk, register GEMM
// ============================================================
__global__ __launch_bounds__(256) void deform_kernel(
    const float* __restrict__ bias,
    float* __restrict__ out)
{
    __shared__ float sS[64][68];     // sampled [pix][c], padded; reused as [oc][pix] for epilogue
    __shared__ float wSh[64][64];    // weight chunk [c][oc]

    int tid = threadIdx.x;
    int b   = blockIdx.z;
    int wo0 = blockIdx.x * 16;
    int ho0 = blockIdx.y * 4;

    // sampling mapping: 64 pixels x 4 channel-groups of 16
    int spix = tid >> 2;
    int cg   = tid & 3;
    int c0   = cg * 16;
    int ho_s = ho0 + (spix >> 4);
    int wo_s = wo0 + (spix & 15);

    // GEMM mapping: 16 tx (oc groups of 4) x 16 ty (pixel groups of 4)
    int tx  = tid & 15;
    int ty  = tid >> 4;
    int oc0 = tx * 4;
    int p0  = ty * 4;

    float acc[4][4];
#pragma unroll
    for (int i = 0; i < 4; ++i)
#pragma unroll
        for (int j = 0; j < 4; ++j) acc[i][j] = 0.f;

    const float* offb = g_off + (size_t)b * OFFC * HW;
    const float* xTb  = g_xT + (size_t)b * HW * CIN;

    for (int kk = 0; kk < KK; ++kk) {
        if (kk > 0) __syncthreads();   // protect sS/wSh from previous GEMM readers

        // ---- stage weight chunk wT[kk] : 4096 floats, contiguous copy ----
        {
            const float4* src = (const float4*)(g_wT + kk * CIN * COUT);
            float4* dst = (float4*)&wSh[0][0];
#pragma unroll
            for (int r = 0; r < 4; ++r)
                dst[tid + r * 256] = src[tid + r * 256];
        }

        // ---- bilinear sampling of 16 channels for this thread's pixel ----
        {
            int ky = kk / 3 - 1;
            int kx = kk % 3 - 1;
            float offy = __ldg(offb + (size_t)(2 * kk)     * HW + ho_s * W_ + wo_s);
            float offx = __ldg(offb + (size_t)(2 * kk + 1) * HW + ho_s * W_ + wo_s);
            float sy = (float)(ho_s + 1 + ky) + offy;
            float sx = (float)(wo_s + 1 + kx) + offx;
            float y0f = floorf(sy), x0f = floorf(sx);
            float wy1 = sy - y0f, wx1 = sx - x0f;
            float wy0 = 1.f - wy1, wx0 = 1.f - wx1;
            int y0 = (int)y0f, x0 = (int)x0f;
            int y1 = y0 + 1,   x1 = x0 + 1;
            bool vy0 = ((unsigned)y0 < (unsigned)H_);
            bool vy1 = ((unsigned)y1 < (unsigned)H_);
            bool vx0 = ((unsigned)x0 < (unsigned)W_);
            bool vx1 = ((unsigned)x1 < (unsigned)W_);
            float w00 = wy0 * wx0, w01 = wy0 * wx1;
            float w10 = wy1 * wx0, w11 = wy1 * wx1;

            float4 sa0 = {0,0,0,0}, sa1 = {0,0,0,0}, sa2 = {0,0,0,0}, sa3 = {0,0,0,0};

            // corner accumulate helper (manually expanded)
#define GATHER_ACC(YI, XI, WW, VALID)                                             \
            if (VALID) {                                                          \
                const float4* p = (const float4*)(xTb + ((size_t)(YI) * W_ + (XI)) * CIN + c0); \
                float4 a = p[0], bb = p[1], cc = p[2], dd = p[3];                 \
                sa0.x += (WW)*a.x;  sa0.y += (WW)*a.y;  sa0.z += (WW)*a.z;  sa0.w += (WW)*a.w;  \
                sa1.x += (WW)*bb.x; sa1.y += (WW)*bb.y; sa1.z += (WW)*bb.z; sa1.w += (WW)*bb.w; \
                sa2.x += (WW)*cc.x; sa2.y += (WW)*cc.y; sa2.z += (WW)*cc.z; sa2.w += (WW)*cc.w; \
                sa3.x += (WW)*dd.x; sa3.y += (WW)*dd.y; sa3.z += (WW)*dd.z; sa3.w += (WW)*dd.w; \
            }

            GATHER_ACC(y0, x0, w00, vy0 && vx0)
            GATHER_ACC(y0, x1, w01, vy0 && vx1)
            GATHER_ACC(y1, x0, w10, vy1 && vx0)
            GATHER_ACC(y1, x1, w11, vy1 && vx1)
#undef GATHER_ACC

            float4* srow = (float4*)&sS[spix][c0];
            srow[0] = sa0; srow[1] = sa1; srow[2] = sa2; srow[3] = sa3;
        }

        __syncthreads();

        // ---- register-tiled GEMM over the 64 channels of this tap ----
#pragma unroll 4
        for (int c = 0; c < CIN; ++c) {
            float4 wv = *(const float4*)&wSh[c][oc0];
            float s0 = sS[p0 + 0][c];
            float s1 = sS[p0 + 1][c];
            float s2 = sS[p0 + 2][c];
            float s3 = sS[p0 + 3][c];
            acc[0][0] += s0 * wv.x; acc[0][1] += s0 * wv.y; acc[0][2] += s0 * wv.z; acc[0][3] += s0 * wv.w;
            acc[1][0] += s1 * wv.x; acc[1][1] += s1 * wv.y; acc[1][2] += s1 * wv.z; acc[1][3] += s1 * wv.w;
            acc[2][0] += s2 * wv.x; acc[2][1] += s2 * wv.y; acc[2][2] += s2 * wv.z; acc[2][3] += s2 * wv.w;
            acc[3][0] += s3 * wv.x; acc[3][1] += s3 * wv.y; acc[3][2] += s3 * wv.z; acc[3][3] += s3 * wv.w;
        }
    }

    // ---- epilogue: transpose through smem for coalesced NCHW stores ----
    __syncthreads();
#pragma unroll
    for (int i = 0; i < 4; ++i)
#pragma unroll
        for (int j = 0; j < 4; ++j)
            sS[oc0 + j][p0 + i] = acc[i][j];
    __syncthreads();

    float* outb = out + (size_t)b * COUT * HW;
#pragma unroll
    for (int r = 0; r < 16; ++r) {
        int idx = r * 256 + tid;
        int oc  = idx >> 6;
        int pix = idx & 63;
        int ho  = ho0 + (pix >> 4);
        int wo  = wo0 + (pix & 15);
        outb[(size_t)oc * HW + ho * W_ + wo] = sS[oc][pix] + __ldg(&bias[oc]);
    }
}

// ============================================================
// launch
// ============================================================
extern "C" void kernel_launch(void* const* d_in, const int* in_sizes, int n_in,
                              void* d_out, int out_size)
{
    const float* x      = (const float*)d_in[0];
    const float* weight = (const float*)d_in[1];
    const float* bias   = (const float*)d_in[2];
    const float* off_w  = (const float*)d_in[3];
    const float* off_b  = (const float*)d_in[4];
    float* out = (float*)d_out;

    // 1) layout transforms
    {
        dim3 grid(HW / 32, CIN / 32, B_);
        dim3 block(32, 8);
        transpose_x_kernel<<<grid, block>>>(x);
    }
    {
        int n = COUT * CIN * KK;
        transpose_w_kernel<<<(n + 255) / 256, 256>>>(weight);
    }
    // 2) offset conv
    {
        dim3 grid(W_ / 32, H_ / 8, B_);
        offset_conv_kernel<<<grid, 256>>>(x, off_w, off_b);
    }
    // 3) deformable conv
    {
        dim3 grid(W_ / 16, H_ / 4, B_);
        deform_kernel<<<grid, 256>>>(bias, out);
    }
}